// round 16
// baseline (speedup 1.0000x reference)
#include <cuda_runtime.h>
#include <cuda_fp16.h>
#include <math.h>
#include <stdint.h>

// Problem constants:
//   query [4,512,1024], memory [4,4096,1024], bias [4,4096]
//   Wq,Wk,Wv,Wo [1024,1024] -> out [4,512,1024] fp32
#define BB 4
#define QL 512
#define KL 4096
#define DD 1024
#define NH 16
#define DH 64

typedef __half half_t;

// ---------------- scratch (static device arrays) ---------------------------
__device__ __align__(128) half_t gi_q16[(size_t)BB * QL * DD];   // query fp16
__device__ __align__(128) half_t gi_m16[(size_t)BB * KL * DD];   // memory fp16
__device__ __align__(128) half_t g_wt[4 * (size_t)DD * DD];      // W^T fp16 (hi only)
__device__ __align__(128) float  g_bias2[(size_t)BB * KL];       // bias*log2e - SHIFT
__device__ __align__(128) half_t g_q16[(size_t)BB * QL * DD];    // Q fp16
__device__ __align__(128) half_t g_k16[(size_t)BB * KL * DD];    // K fp16
__device__ __align__(128) half_t g_v16[(size_t)BB * KL * DD];    // V fp16
__device__ __align__(128) half_t g_a16[(size_t)BB * QL * DD];    // attn out fp16

// Constant softmax-argument shift (cancels exactly in normalization; moves
// the heavy-weight exp arguments near 0 where fp16 ulp is smallest).
#define ARG_SHIFT 7.0f

// ---------------- PTX helpers ------------------------------------------------
__device__ __forceinline__ uint32_t smem_u32(const void* p) {
    uint32_t a;
    asm("{ .reg .u64 t; cvta.to.shared.u64 t, %1; cvt.u32.u64 %0, t; }" : "=r"(a) : "l"(p));
    return a;
}
__device__ __forceinline__ void cp16(uint32_t dst, const void* src) {
    asm volatile("cp.async.cg.shared.global [%0], [%1], 16;" :: "r"(dst), "l"(src));
}
#define CP_COMMIT() asm volatile("cp.async.commit_group;" ::: "memory")
#define CP_WAIT2()  asm volatile("cp.async.wait_group 2;" ::: "memory")
#define CP_WAIT1()  asm volatile("cp.async.wait_group 1;" ::: "memory")
#define CP_WAIT0()  asm volatile("cp.async.wait_group 0;" ::: "memory")

__device__ __forceinline__ void ldsm_x4(uint32_t (&r)[4], uint32_t addr) {
    asm volatile("ldmatrix.sync.aligned.m8n8.x4.shared.b16 {%0,%1,%2,%3}, [%4];"
        : "=r"(r[0]), "=r"(r[1]), "=r"(r[2]), "=r"(r[3]) : "r"(addr));
}
__device__ __forceinline__ void ldsm_x4t(uint32_t (&r)[4], uint32_t addr) {
    asm volatile("ldmatrix.sync.aligned.m8n8.x4.trans.shared.b16 {%0,%1,%2,%3}, [%4];"
        : "=r"(r[0]), "=r"(r[1]), "=r"(r[2]), "=r"(r[3]) : "r"(addr));
}
__device__ __forceinline__ void mma_f16(float (&d)[4], const uint32_t (&a)[4],
                                        uint32_t b0, uint32_t b1) {
    asm volatile(
        "mma.sync.aligned.m16n8k16.row.col.f32.f16.f16.f32 "
        "{%0,%1,%2,%3}, {%4,%5,%6,%7}, {%8,%9}, {%0,%1,%2,%3};"
        : "+f"(d[0]), "+f"(d[1]), "+f"(d[2]), "+f"(d[3])
        : "r"(a[0]), "r"(a[1]), "r"(a[2]), "r"(a[3]), "r"(b0), "r"(b1));
}
__device__ __forceinline__ uint32_t packh(float a, float b) {
    __half2 t = __floats2half2_rn(a, b);
    return *reinterpret_cast<uint32_t*>(&t);
}
// paired exp2 on the MUFU pipe: one op computes two fp16 exps, output is
// already a packed fp16x2 P-fragment.
__device__ __forceinline__ uint32_t mexp2h2(uint32_t a) {
    uint32_t r;
    asm("ex2.approx.f16x2 %0, %1;" : "=r"(r) : "r"(a));
    return r;
}

// ---------------- single-pass fp16 MMA GEMM -----------------------------------
// C[M,1024] = A[M,1024] @ W[1024,1024]; A fp16 [M,K], W^T fp16 [N,K].
// CTA tile = (MT*32) x 128, BK=32, 128 threads (2x2 warps). 3-stage cp.async
// pipeline. MODE 0: fp32 out. MODE 1: fp16 out.
#define GP 80             // fp16 tile pitch bytes (32 fp16 + pad)
#define BMATB (128 * GP)  // B tile bytes (10240)

__host__ __device__ constexpr int gstage_bytes(int MT) {
    return MT * 32 * GP + BMATB;
}
__host__ __device__ constexpr int gsmem_bytes(int MT) {
    return 3 * gstage_bytes(MT);
}

template <int MT>
__device__ __forceinline__ void gemm_load_stage(
    uint32_t sb, int st, int t,
    const half_t* __restrict__ A, const half_t* __restrict__ B,
    int m0, int n0, int k0)
{
    const int GS = gstage_bytes(MT);
    const int AM = MT * 32 * GP;
    uint32_t base = sb + st * GS;
    #pragma unroll
    for (int i = 0; i < MT; ++i) {
        int ch = t + i * 128;
        int row = ch >> 2, seg = ch & 3;
        cp16(base + row * GP + seg * 16,
             A + (size_t)(m0 + row) * DD + k0 + seg * 8);
    }
    #pragma unroll
    for (int i = 0; i < 4; ++i) {
        int ch = t + i * 128;
        int row = ch >> 2, seg = ch & 3;
        cp16(base + AM + row * GP + seg * 16,
             B + (size_t)(n0 + row) * DD + k0 + seg * 8);
    }
}

template <int MODE, int MT>
__global__ __launch_bounds__(128, 2) void gemm_mma(
    const half_t* __restrict__ A, const half_t* __restrict__ B,
    float* __restrict__ Cf, half_t* __restrict__ Ch)
{
    extern __shared__ char smem[];
    const uint32_t sb = smem_u32(smem);
    const int GS = gstage_bytes(MT);
    const int AM = MT * 32 * GP;
    const int t = threadIdx.x;
    const int lane = t & 31, wid = t >> 5;
    const int wm = wid >> 1, wn = wid & 1;
    const int n0 = blockIdx.x * 128, m0 = blockIdx.y * (MT * 32);

    float acc[MT][8][4] = {};

    gemm_load_stage<MT>(sb, 0, t, A, B, m0, n0, 0);
    CP_COMMIT();
    gemm_load_stage<MT>(sb, 1, t, A, B, m0, n0, 32);
    CP_COMMIT();
    gemm_load_stage<MT>(sb, 2, t, A, B, m0, n0, 64);
    CP_COMMIT();

    int st = 0;
    for (int it = 0; it < 32; ++it) {
        CP_WAIT2();
        __syncthreads();

        const uint32_t sA = sb + st * GS;
        const uint32_t sB = sA + AM;

        #pragma unroll
        for (int kt = 0; kt < 2; ++kt) {
            uint32_t a[MT][4];
            #pragma unroll
            for (int mt = 0; mt < MT; ++mt) {
                uint32_t row = wm * (MT * 16) + mt * 16 + (lane & 15);
                uint32_t col = kt * 16 + ((lane >> 4) << 3);
                ldsm_x4(a[mt], sA + row * GP + col * 2);
            }
            #pragma unroll
            for (int nb = 0; nb < 4; ++nb) {
                uint32_t bh[4];
                uint32_t row = wn * 64 + nb * 16 + ((lane >> 4) << 3) + (lane & 7);
                uint32_t col = kt * 16 + (lane & 8);
                ldsm_x4(bh, sB + row * GP + col * 2);
                #pragma unroll
                for (int mt = 0; mt < MT; ++mt) {
                    mma_f16(acc[mt][2 * nb],     a[mt], bh[0], bh[1]);
                    mma_f16(acc[mt][2 * nb + 1], a[mt], bh[2], bh[3]);
                }
            }
        }
        __syncthreads();
        if (it + 3 < 32)
            gemm_load_stage<MT>(sb, st, t, A, B, m0, n0, (it + 3) * 32);
        CP_COMMIT();
        st = (st == 2) ? 0 : st + 1;
    }

    #pragma unroll
    for (int mt = 0; mt < MT; ++mt)
        #pragma unroll
        for (int nt = 0; nt < 8; ++nt) {
            int r = m0 + wm * (MT * 16) + mt * 16 + (lane >> 2);
            int c = n0 + wn * 64 + nt * 8 + (lane & 3) * 2;
            float v0 = acc[mt][nt][0], v1 = acc[mt][nt][1];
            float v2 = acc[mt][nt][2], v3 = acc[mt][nt][3];
            if (MODE == 0) {
                *reinterpret_cast<float2*>(Cf + (size_t)r * DD + c) = make_float2(v0, v1);
                *reinterpret_cast<float2*>(Cf + (size_t)(r + 8) * DD + c) = make_float2(v2, v3);
            } else {
                *reinterpret_cast<uint32_t*>(Ch + (size_t)r * DD + c) = packh(v0, v1);
                *reinterpret_cast<uint32_t*>(Ch + (size_t)(r + 8) * DD + c) = packh(v2, v3);
            }
        }
}

// ---------------- fused attention on mma.sync --------------------------------
// One launch per BATCH. CTA = (128 q-rows, head); 256 thr, warp = 16 q-rows.
// S = Q*K single pass; w = exp2(S*C1 + bias2 - SHIFT) via paired MUFU
// ex2.approx.f16x2 (shift folded into bias2; cancels in normalization);
// O += P*V single pass.
#define AP 144
#define AMATB (128 * AP)
#define A_SQ 0
#define A_KV0 AMATB
#define A_STAGE (2 * AMATB)
#define A_SBIAS (A_KV0 + 2 * A_STAGE)
#define ATT_SMEM (A_SBIAS + 2 * 512)

__device__ __forceinline__ void attn_load_kv(
    uint32_t sb, int st, int t,
    const half_t* __restrict__ k16, const half_t* __restrict__ v16,
    const float* __restrict__ bias2, size_t krow0, int hcol)
{
    uint32_t base = sb + A_KV0 + st * A_STAGE;
    #pragma unroll
    for (int i = 0; i < 4; ++i) {
        int ch = t + i * 256;
        int row = ch >> 3, seg = ch & 7;
        size_t ga = (krow0 + row) * DD + hcol + seg * 8;
        uint32_t d = row * AP + seg * 16;
        cp16(base + d, k16 + ga);
        cp16(base + AMATB + d, v16 + ga);
    }
    if (t < 32) cp16(sb + A_SBIAS + st * 512 + t * 16, bias2 + krow0 + t * 4);
}

__global__ __launch_bounds__(256) void attn_mma(
    const half_t* __restrict__ q16,
    const half_t* __restrict__ k16, const half_t* __restrict__ v16,
    const float* __restrict__ bias2, half_t* __restrict__ o16)
{
    extern __shared__ char smem[];
    const uint32_t sb = smem_u32(smem);
    const int t = threadIdx.x;
    const int lane = t & 31, wid = t >> 5;
    const int qt = blockIdx.x, h = blockIdx.y;
    const int hcol = h * DH;
    const size_t qrow0 = (size_t)qt * 128;
    const float C1 = 0.125f * 1.44269504f;

    #pragma unroll
    for (int i = 0; i < 4; ++i) {
        int ch = t + i * 256;
        int row = ch >> 3, seg = ch & 7;
        size_t ga = (qrow0 + row) * DD + hcol + seg * 8;
        cp16(sb + A_SQ + row * AP + seg * 16, q16 + ga);
    }
    attn_load_kv(sb, 0, t, k16, v16, bias2, 0, hcol);
    CP_COMMIT();
    attn_load_kv(sb, 1, t, k16, v16, bias2, 128, hcol);
    CP_COMMIT();

    CP_WAIT1();
    __syncthreads();

    uint32_t qh[4][4];
    #pragma unroll
    for (int dt = 0; dt < 4; ++dt) {
        uint32_t row = wid * 16 + (lane & 15);
        uint32_t col = dt * 16 + ((lane >> 4) << 3);
        ldsm_x4(qh[dt], sb + A_SQ + row * AP + col * 2);
    }

    float oacc[8][4] = {};
    float l0 = 0.f, l1 = 0.f;

    for (int it = 0; it < 32; ++it) {
        if (it > 0) {
            if (it < 31) { CP_WAIT1(); } else { CP_WAIT0(); }
            __syncthreads();
        }
        const int st = it & 1;
        const uint32_t sK = sb + A_KV0 + st * A_STAGE;
        const uint32_t sV = sK + AMATB;

        // S = Q K^T  (single pass)
        float w[16][4] = {};
        #pragma unroll
        for (int dt = 0; dt < 4; ++dt) {
            #pragma unroll
            for (int np = 0; np < 8; ++np) {
                uint32_t kb[4];
                uint32_t row = np * 16 + ((lane >> 4) << 3) + (lane & 7);
                uint32_t col = dt * 16 + (lane & 8);
                ldsm_x4(kb, sK + row * AP + col * 2);
                mma_f16(w[2 * np],     qh[dt], kb[0], kb[1]);
                mma_f16(w[2 * np + 1], qh[dt], kb[2], kb[3]);
            }
        }

        // P = exp2(S*C1 + bias2) via paired f16x2 MUFU -> packed P fragments;
        // the -SHIFT folded into bias2 keeps heavy args near 0 (small ulp).
        uint32_t ph[8][4];
        #pragma unroll
        for (int g = 0; g < 8; ++g) {
            #pragma unroll
            for (int hf = 0; hf < 2; ++hf) {
                const int nt = 2 * g + hf;
                float2 bv = *reinterpret_cast<const float2*>(
                    smem + A_SBIAS + st * 512 + (nt * 8 + (lane & 3) * 2) * 4);
                uint32_t a01 = packh(fmaf(w[nt][0], C1, bv.x),
                                     fmaf(w[nt][1], C1, bv.y));
                uint32_t a23 = packh(fmaf(w[nt][2], C1, bv.x),
                                     fmaf(w[nt][3], C1, bv.y));
                uint32_t h01 = mexp2h2(a01);
                uint32_t h23 = mexp2h2(a23);
                ph[g][2 * hf]     = h01;
                ph[g][2 * hf + 1] = h23;
                __half2 t01 = *reinterpret_cast<__half2*>(&h01);
                __half2 t23 = *reinterpret_cast<__half2*>(&h23);
                l0 += __low2float(t01) + __high2float(t01);
                l1 += __low2float(t23) + __high2float(t23);
            }
        }

        // O += P V
        #pragma unroll
        for (int g = 0; g < 8; ++g) {
            #pragma unroll
            for (int np = 0; np < 4; ++np) {
                uint32_t vb[4];
                uint32_t row = g * 16 + (lane & 15);
                uint32_t col = np * 16 + ((lane >> 4) << 3);
                ldsm_x4t(vb, sV + row * AP + col * 2);
                mma_f16(oacc[2 * np],     ph[g], vb[0], vb[1]);
                mma_f16(oacc[2 * np + 1], ph[g], vb[2], vb[3]);
            }
        }

        __syncthreads();
        if (it + 2 < 32) {
            attn_load_kv(sb, st, t, k16, v16, bias2, (size_t)(it + 2) * 128, hcol);
            CP_COMMIT();
        } else {
            CP_COMMIT();
        }
    }

    l0 += __shfl_xor_sync(0xffffffffu, l0, 1);
    l0 += __shfl_xor_sync(0xffffffffu, l0, 2);
    l1 += __shfl_xor_sync(0xffffffffu, l1, 1);
    l1 += __shfl_xor_sync(0xffffffffu, l1, 2);
    float inv0 = 1.0f / l0, inv1 = 1.0f / l1;

    size_t r0 = qrow0 + wid * 16 + (lane >> 2);
    size_t r1 = r0 + 8;
    #pragma unroll
    for (int nt = 0; nt < 8; ++nt) {
        int c = hcol + nt * 8 + (lane & 3) * 2;
        *reinterpret_cast<uint32_t*>(o16 + r0 * DD + c) =
            packh(oacc[nt][0] * inv0, oacc[nt][1] * inv0);
        *reinterpret_cast<uint32_t*>(o16 + r1 * DD + c) =
            packh(oacc[nt][2] * inv1, oacc[nt][3] * inv1);
    }
}

// ---------------- conversion kernels ----------------------------------------
__global__ void cvt16_kernel(const float4* __restrict__ x,
                             __half2* __restrict__ y, int n4)
{
    int i = blockIdx.x * blockDim.x + threadIdx.x;
    if (i >= n4) return;
    float4 v = x[i];
    y[2 * i]     = __floats2half2_rn(v.x, v.y);
    y[2 * i + 1] = __floats2half2_rn(v.z, v.w);
}

__global__ void bias_scale_kernel(const float* __restrict__ b,
                                  float* __restrict__ b2, int n)
{
    int i = blockIdx.x * blockDim.x + threadIdx.x;
    if (i < n) b2[i] = fmaf(b[i], 1.44269504f, -ARG_SHIFT);
}

// 4x W[1024,1024] fp32 row-major -> W^T fp16 [N,K], batched over z (hi only)
__global__ void transpose4(const float* __restrict__ W0,
                           const float* __restrict__ W1,
                           const float* __restrict__ W2,
                           const float* __restrict__ W3,
                           half_t* __restrict__ T)
{
    __shared__ float tl[32][33];
    const int tx = threadIdx.x, ty = threadIdx.y;
    const int n0 = blockIdx.x * 32, k0 = blockIdx.y * 32;
    const int z = blockIdx.z;
    const float* W = (z == 0) ? W0 : (z == 1) ? W1 : (z == 2) ? W2 : W3;
    half_t* th = T + (size_t)z * DD * DD;
    #pragma unroll
    for (int i = 0; i < 4; ++i)
        tl[ty + i * 8][tx] = W[(size_t)(k0 + ty + i * 8) * DD + n0 + tx];
    __syncthreads();
    #pragma unroll
    for (int i = 0; i < 4; ++i) {
        float v = tl[tx][ty + i * 8];
        th[(size_t)(n0 + ty + i * 8) * DD + k0 + tx] = __float2half_rn(v);
    }
}

// ---------------- host launch -------------------------------------------------
extern "C" void kernel_launch(void* const* d_in, const int* in_sizes, int n_in,
                              void* d_out, int out_size)
{
    const float* query  = (const float*)d_in[0];
    const float* memory = (const float*)d_in[1];
    const float* bias   = (const float*)d_in[2];
    const float* W0 = (const float*)d_in[3];
    const float* W1 = (const float*)d_in[4];
    const float* W2 = (const float*)d_in[5];
    const float* W3 = (const float*)d_in[6];
    float* out = (float*)d_out;

    half_t *iq16, *im16, *wt, *q16, *k16, *v16, *a16;
    float* bias2;
    cudaGetSymbolAddress((void**)&iq16, gi_q16);
    cudaGetSymbolAddress((void**)&im16, gi_m16);
    cudaGetSymbolAddress((void**)&wt, g_wt);
    cudaGetSymbolAddress((void**)&bias2, g_bias2);
    cudaGetSymbolAddress((void**)&q16, g_q16);
    cudaGetSymbolAddress((void**)&k16, g_k16);
    cudaGetSymbolAddress((void**)&v16, g_v16);
    cudaGetSymbolAddress((void**)&a16, g_a16);

    const int SM_S = gsmem_bytes(2);
    const int SM_L = gsmem_bytes(4);

    static cudaStream_t s1 = nullptr, s2 = nullptr, s3 = nullptr;
    static cudaEvent_t ev[10] = {};
    static int attr_set = 0;
    if (!attr_set) {
        cudaFuncSetAttribute((const void*)gemm_mma<1, 2>,
                             cudaFuncAttributeMaxDynamicSharedMemorySize, SM_S);
        cudaFuncSetAttribute((const void*)gemm_mma<0, 2>,
                             cudaFuncAttributeMaxDynamicSharedMemorySize, SM_S);
        cudaFuncSetAttribute((const void*)gemm_mma<1, 4>,
                             cudaFuncAttributeMaxDynamicSharedMemorySize, SM_L);
        cudaFuncSetAttribute((const void*)attn_mma,
                             cudaFuncAttributeMaxDynamicSharedMemorySize, ATT_SMEM);
        cudaStreamCreateWithFlags(&s1, cudaStreamNonBlocking);
        cudaStreamCreateWithFlags(&s2, cudaStreamNonBlocking);
        cudaStreamCreateWithFlags(&s3, cudaStreamNonBlocking);
        for (int i = 0; i < 10; ++i)
            cudaEventCreateWithFlags(&ev[i], cudaEventDisableTiming);
        attr_set = 1;
    }
    cudaStream_t sd = (cudaStream_t)0;
    cudaEvent_t eF = ev[0], eT = ev[1], eC1 = ev[2], eQ = ev[3];
    cudaEvent_t eKV1 = ev[4], eKV2 = ev[5];

    const size_t HALF_M = (size_t)(BB / 2) * KL;

    // ---- fork ----
    cudaEventRecord(eF, sd);
    cudaStreamWaitEvent(s1, eF, 0);
    cudaStreamWaitEvent(s2, eF, 0);
    cudaStreamWaitEvent(s3, eF, 0);

    // s2: weights + bias prescale (with folded -ARG_SHIFT)
    {
        dim3 thr(32, 8), grid(DD / 32, DD / 32, 4);
        transpose4<<<grid, thr, 0, s2>>>(W0, W1, W2, W3, wt);
        bias_scale_kernel<<<(BB * KL) / 256, 256, 0, s2>>>(bias, bias2, BB * KL);
        cudaEventRecord(eT, s2);
    }
    // s1: query -> fp16, then Q projection (single pass)
    {
        int n4 = (BB * QL * DD) / 4;
        cvt16_kernel<<<n4 / 256, 256, 0, s1>>>((const float4*)query, (__half2*)iq16, n4);
        cudaStreamWaitEvent(s1, eT, 0);
        dim3 grid(DD / 128, (BB * QL) / 64);
        gemm_mma<1, 2><<<grid, 128, SM_S, s1>>>(iq16, wt, nullptr, q16);
        cudaEventRecord(eQ, s1);
    }
    // sd: memory half 1 -> fp16, K1, V1 (covers batches 0,1)
    {
        int n4h = (int)(HALF_M * DD / 4);
        cvt16_kernel<<<n4h / 256, 256, 0, sd>>>((const float4*)memory, (__half2*)im16, n4h);
        cudaEventRecord(eC1, sd);
        cudaStreamWaitEvent(sd, eT, 0);
        dim3 grid(DD / 128, (int)(HALF_M / 128));
        gemm_mma<1, 4><<<grid, 128, SM_L, sd>>>(im16, wt + (size_t)DD * DD, nullptr, k16);
        gemm_mma<1, 4><<<grid, 128, SM_L, sd>>>(im16, wt + 2 * (size_t)DD * DD, nullptr, v16);
        cudaEventRecord(eKV1, sd);
    }
    // s3: memory half 2 -> fp16, K2, V2
    {
        cudaStreamWaitEvent(s3, eC1, 0);
        int n4h = (int)(HALF_M * DD / 4);
        cvt16_kernel<<<n4h / 256, 256, 0, s3>>>(
            (const float4*)(memory + HALF_M * DD), (__half2*)(im16 + HALF_M * DD), n4h);
        cudaStreamWaitEvent(s3, eT, 0);
        dim3 grid(DD / 128, (int)(HALF_M / 128));
        gemm_mma<1, 4><<<grid, 128, SM_L, s3>>>(im16 + HALF_M * DD,
                                                wt + (size_t)DD * DD, nullptr,
                                                k16 + HALF_M * DD);
        gemm_mma<1, 4><<<grid, 128, SM_L, s3>>>(im16 + HALF_M * DD,
                                                wt + 2 * (size_t)DD * DD, nullptr,
                                                v16 + HALF_M * DD);
        cudaEventRecord(eKV2, s3);
    }

    // ---- per-batch attention + O-projection on 4 streams ----
    cudaStream_t bst[BB] = {sd, s2, s3, s1};
    for (int b = 0; b < BB; ++b) {
        cudaStream_t s = bst[b];
        if (b < 2) cudaStreamWaitEvent(s, eKV1, 0);
        else       cudaStreamWaitEvent(s, eKV2, 0);
        cudaStreamWaitEvent(s, eQ, 0);

        size_t qo = (size_t)b * QL * DD;
        size_t ko = (size_t)b * KL * DD;
        {
            dim3 grid(QL / 128, NH, 1);
            attn_mma<<<grid, 256, ATT_SMEM, s>>>(q16 + qo, k16 + ko, v16 + ko,
                                                 bias2 + (size_t)b * KL, a16 + qo);
        }
        {
            dim3 grid(DD / 128, QL / 64);
            gemm_mma<0, 2><<<grid, 128, SM_S, s>>>(a16 + qo, wt + 3 * (size_t)DD * DD,
                                                   out + qo, nullptr);
        }
        if (s != sd) {
            cudaEventRecord(ev[6 + b], s);
            cudaStreamWaitEvent(sd, ev[6 + b], 0);
        }
    }
}

// round 17
// speedup vs baseline: 1.0126x; 1.0126x over previous
#include <cuda_runtime.h>
#include <cuda_fp16.h>
#include <math.h>
#include <stdint.h>

// Problem constants:
//   query [4,512,1024], memory [4,4096,1024], bias [4,4096]
//   Wq,Wk,Wv,Wo [1024,1024] -> out [4,512,1024] fp32
#define BB 4
#define QL 512
#define KL 4096
#define DD 1024
#define NH 16
#define DH 64

typedef __half half_t;

// ---------------- scratch (static device arrays) ---------------------------
__device__ __align__(128) half_t gi_q16[(size_t)BB * QL * DD];   // query fp16
__device__ __align__(128) half_t gi_m16[(size_t)BB * KL * DD];   // memory fp16
__device__ __align__(128) half_t g_wt[4 * (size_t)DD * DD];      // W^T fp16 (hi only)
__device__ __align__(128) float  g_bias2[(size_t)BB * KL];       // bias*log2e - SHIFT
__device__ __align__(128) half_t g_q16[(size_t)BB * QL * DD];    // Q fp16
__device__ __align__(128) half_t g_k16[(size_t)BB * KL * DD];    // K fp16
__device__ __align__(128) half_t g_v16[(size_t)BB * KL * DD];    // V fp16
__device__ __align__(128) half_t g_a16[(size_t)BB * QL * DD];    // attn out fp16

// Constant softmax-argument shift (cancels exactly in normalization; moves
// the heavy-weight exp arguments near 0 where fp16 ulp is smallest).
#define ARG_SHIFT 7.0f

// ---------------- PTX helpers ------------------------------------------------
__device__ __forceinline__ uint32_t smem_u32(const void* p) {
    uint32_t a;
    asm("{ .reg .u64 t; cvta.to.shared.u64 t, %1; cvt.u32.u64 %0, t; }" : "=r"(a) : "l"(p));
    return a;
}
__device__ __forceinline__ void cp16(uint32_t dst, const void* src) {
    asm volatile("cp.async.cg.shared.global [%0], [%1], 16;" :: "r"(dst), "l"(src));
}
#define CP_COMMIT() asm volatile("cp.async.commit_group;" ::: "memory")
#define CP_WAIT2()  asm volatile("cp.async.wait_group 2;" ::: "memory")
#define CP_WAIT1()  asm volatile("cp.async.wait_group 1;" ::: "memory")
#define CP_WAIT0()  asm volatile("cp.async.wait_group 0;" ::: "memory")

__device__ __forceinline__ void ldsm_x4(uint32_t (&r)[4], uint32_t addr) {
    asm volatile("ldmatrix.sync.aligned.m8n8.x4.shared.b16 {%0,%1,%2,%3}, [%4];"
        : "=r"(r[0]), "=r"(r[1]), "=r"(r[2]), "=r"(r[3]) : "r"(addr));
}
__device__ __forceinline__ void ldsm_x4t(uint32_t (&r)[4], uint32_t addr) {
    asm volatile("ldmatrix.sync.aligned.m8n8.x4.trans.shared.b16 {%0,%1,%2,%3}, [%4];"
        : "=r"(r[0]), "=r"(r[1]), "=r"(r[2]), "=r"(r[3]) : "r"(addr));
}
__device__ __forceinline__ void mma_f16(float (&d)[4], const uint32_t (&a)[4],
                                        uint32_t b0, uint32_t b1) {
    asm volatile(
        "mma.sync.aligned.m16n8k16.row.col.f32.f16.f16.f32 "
        "{%0,%1,%2,%3}, {%4,%5,%6,%7}, {%8,%9}, {%0,%1,%2,%3};"
        : "+f"(d[0]), "+f"(d[1]), "+f"(d[2]), "+f"(d[3])
        : "r"(a[0]), "r"(a[1]), "r"(a[2]), "r"(a[3]), "r"(b0), "r"(b1));
}
__device__ __forceinline__ uint32_t packh(float a, float b) {
    __half2 t = __floats2half2_rn(a, b);
    return *reinterpret_cast<uint32_t*>(&t);
}
// paired exp2 on the MUFU pipe: one op computes two fp16 exps, output is
// already a packed fp16x2 P-fragment.
__device__ __forceinline__ uint32_t mexp2h2(uint32_t a) {
    uint32_t r;
    asm("ex2.approx.f16x2 %0, %1;" : "=r"(r) : "r"(a));
    return r;
}

// ---------------- single-pass fp16 MMA GEMM -----------------------------------
// C[M,1024] = A[M,1024] @ W[1024,1024]; A fp16 [M,K], W^T fp16 [N,K].
// CTA tile = (MT*32) x 128, BK=32, 128 threads (2x2 warps). 3-stage cp.async
// pipeline. MODE 0: fp32 out. MODE 1: fp16 out.
// blockIdx.z selects (B,Ch) vs (B2,Ch2) so K and V projections share one
// launch (same A tile stream, better wave packing).
#define GP 80             // fp16 tile pitch bytes (32 fp16 + pad)
#define BMATB (128 * GP)  // B tile bytes (10240)

__host__ __device__ constexpr int gstage_bytes(int MT) {
    return MT * 32 * GP + BMATB;
}
__host__ __device__ constexpr int gsmem_bytes(int MT) {
    return 3 * gstage_bytes(MT);
}

template <int MT>
__device__ __forceinline__ void gemm_load_stage(
    uint32_t sb, int st, int t,
    const half_t* __restrict__ A, const half_t* __restrict__ B,
    int m0, int n0, int k0)
{
    const int GS = gstage_bytes(MT);
    const int AM = MT * 32 * GP;
    uint32_t base = sb + st * GS;
    #pragma unroll
    for (int i = 0; i < MT; ++i) {
        int ch = t + i * 128;
        int row = ch >> 2, seg = ch & 3;
        cp16(base + row * GP + seg * 16,
             A + (size_t)(m0 + row) * DD + k0 + seg * 8);
    }
    #pragma unroll
    for (int i = 0; i < 4; ++i) {
        int ch = t + i * 128;
        int row = ch >> 2, seg = ch & 3;
        cp16(base + AM + row * GP + seg * 16,
             B + (size_t)(n0 + row) * DD + k0 + seg * 8);
    }
}

template <int MODE, int MT>
__global__ __launch_bounds__(128, 2) void gemm_mma(
    const half_t* __restrict__ A, const half_t* __restrict__ B,
    float* __restrict__ Cf, half_t* __restrict__ Ch,
    const half_t* __restrict__ B2 = nullptr, half_t* __restrict__ Ch2 = nullptr)
{
    extern __shared__ char smem[];
    const uint32_t sb = smem_u32(smem);
    const int GS = gstage_bytes(MT);
    const int AM = MT * 32 * GP;
    const int t = threadIdx.x;
    const int lane = t & 31, wid = t >> 5;
    const int wm = wid >> 1, wn = wid & 1;
    const int n0 = blockIdx.x * 128, m0 = blockIdx.y * (MT * 32);
    const half_t* Bp = (blockIdx.z == 0) ? B : B2;
    half_t* Chp = (blockIdx.z == 0) ? Ch : Ch2;

    float acc[MT][8][4] = {};

    gemm_load_stage<MT>(sb, 0, t, A, Bp, m0, n0, 0);
    CP_COMMIT();
    gemm_load_stage<MT>(sb, 1, t, A, Bp, m0, n0, 32);
    CP_COMMIT();
    gemm_load_stage<MT>(sb, 2, t, A, Bp, m0, n0, 64);
    CP_COMMIT();

    int st = 0;
    for (int it = 0; it < 32; ++it) {
        CP_WAIT2();
        __syncthreads();

        const uint32_t sA = sb + st * GS;
        const uint32_t sB = sA + AM;

        #pragma unroll
        for (int kt = 0; kt < 2; ++kt) {
            uint32_t a[MT][4];
            #pragma unroll
            for (int mt = 0; mt < MT; ++mt) {
                uint32_t row = wm * (MT * 16) + mt * 16 + (lane & 15);
                uint32_t col = kt * 16 + ((lane >> 4) << 3);
                ldsm_x4(a[mt], sA + row * GP + col * 2);
            }
            #pragma unroll
            for (int nb = 0; nb < 4; ++nb) {
                uint32_t bh[4];
                uint32_t row = wn * 64 + nb * 16 + ((lane >> 4) << 3) + (lane & 7);
                uint32_t col = kt * 16 + (lane & 8);
                ldsm_x4(bh, sB + row * GP + col * 2);
                #pragma unroll
                for (int mt = 0; mt < MT; ++mt) {
                    mma_f16(acc[mt][2 * nb],     a[mt], bh[0], bh[1]);
                    mma_f16(acc[mt][2 * nb + 1], a[mt], bh[2], bh[3]);
                }
            }
        }
        __syncthreads();
        if (it + 3 < 32)
            gemm_load_stage<MT>(sb, st, t, A, Bp, m0, n0, (it + 3) * 32);
        CP_COMMIT();
        st = (st == 2) ? 0 : st + 1;
    }

    #pragma unroll
    for (int mt = 0; mt < MT; ++mt)
        #pragma unroll
        for (int nt = 0; nt < 8; ++nt) {
            int r = m0 + wm * (MT * 16) + mt * 16 + (lane >> 2);
            int c = n0 + wn * 64 + nt * 8 + (lane & 3) * 2;
            float v0 = acc[mt][nt][0], v1 = acc[mt][nt][1];
            float v2 = acc[mt][nt][2], v3 = acc[mt][nt][3];
            if (MODE == 0) {
                *reinterpret_cast<float2*>(Cf + (size_t)r * DD + c) = make_float2(v0, v1);
                *reinterpret_cast<float2*>(Cf + (size_t)(r + 8) * DD + c) = make_float2(v2, v3);
            } else {
                *reinterpret_cast<uint32_t*>(Chp + (size_t)r * DD + c) = packh(v0, v1);
                *reinterpret_cast<uint32_t*>(Chp + (size_t)(r + 8) * DD + c) = packh(v2, v3);
            }
        }
}

// ---------------- fused attention on mma.sync --------------------------------
// One launch per BATCH. CTA = (128 q-rows, head); 256 thr, warp = 16 q-rows.
// S = Q*K single pass; w = exp2(S*C1 + bias2 - SHIFT) via paired MUFU
// ex2.approx.f16x2 (shift folded into bias2; cancels in normalization);
// O += P*V single pass.
#define AP 144
#define AMATB (128 * AP)
#define A_SQ 0
#define A_KV0 AMATB
#define A_STAGE (2 * AMATB)
#define A_SBIAS (A_KV0 + 2 * A_STAGE)
#define ATT_SMEM (A_SBIAS + 2 * 512)

__device__ __forceinline__ void attn_load_kv(
    uint32_t sb, int st, int t,
    const half_t* __restrict__ k16, const half_t* __restrict__ v16,
    const float* __restrict__ bias2, size_t krow0, int hcol)
{
    uint32_t base = sb + A_KV0 + st * A_STAGE;
    #pragma unroll
    for (int i = 0; i < 4; ++i) {
        int ch = t + i * 256;
        int row = ch >> 3, seg = ch & 7;
        size_t ga = (krow0 + row) * DD + hcol + seg * 8;
        uint32_t d = row * AP + seg * 16;
        cp16(base + d, k16 + ga);
        cp16(base + AMATB + d, v16 + ga);
    }
    if (t < 32) cp16(sb + A_SBIAS + st * 512 + t * 16, bias2 + krow0 + t * 4);
}

__global__ __launch_bounds__(256) void attn_mma(
    const half_t* __restrict__ q16,
    const half_t* __restrict__ k16, const half_t* __restrict__ v16,
    const float* __restrict__ bias2, half_t* __restrict__ o16)
{
    extern __shared__ char smem[];
    const uint32_t sb = smem_u32(smem);
    const int t = threadIdx.x;
    const int lane = t & 31, wid = t >> 5;
    const int qt = blockIdx.x, h = blockIdx.y;
    const int hcol = h * DH;
    const size_t qrow0 = (size_t)qt * 128;
    const float C1 = 0.125f * 1.44269504f;

    #pragma unroll
    for (int i = 0; i < 4; ++i) {
        int ch = t + i * 256;
        int row = ch >> 3, seg = ch & 7;
        size_t ga = (qrow0 + row) * DD + hcol + seg * 8;
        cp16(sb + A_SQ + row * AP + seg * 16, q16 + ga);
    }
    attn_load_kv(sb, 0, t, k16, v16, bias2, 0, hcol);
    CP_COMMIT();
    attn_load_kv(sb, 1, t, k16, v16, bias2, 128, hcol);
    CP_COMMIT();

    CP_WAIT1();
    __syncthreads();

    uint32_t qh[4][4];
    #pragma unroll
    for (int dt = 0; dt < 4; ++dt) {
        uint32_t row = wid * 16 + (lane & 15);
        uint32_t col = dt * 16 + ((lane >> 4) << 3);
        ldsm_x4(qh[dt], sb + A_SQ + row * AP + col * 2);
    }

    float oacc[8][4] = {};
    float l0 = 0.f, l1 = 0.f;

    for (int it = 0; it < 32; ++it) {
        if (it > 0) {
            if (it < 31) { CP_WAIT1(); } else { CP_WAIT0(); }
            __syncthreads();
        }
        const int st = it & 1;
        const uint32_t sK = sb + A_KV0 + st * A_STAGE;
        const uint32_t sV = sK + AMATB;

        // S = Q K^T  (single pass)
        float w[16][4] = {};
        #pragma unroll
        for (int dt = 0; dt < 4; ++dt) {
            #pragma unroll
            for (int np = 0; np < 8; ++np) {
                uint32_t kb[4];
                uint32_t row = np * 16 + ((lane >> 4) << 3) + (lane & 7);
                uint32_t col = dt * 16 + (lane & 8);
                ldsm_x4(kb, sK + row * AP + col * 2);
                mma_f16(w[2 * np],     qh[dt], kb[0], kb[1]);
                mma_f16(w[2 * np + 1], qh[dt], kb[2], kb[3]);
            }
        }

        // P = exp2(S*C1 + bias2) via paired f16x2 MUFU -> packed P fragments
        uint32_t ph[8][4];
        #pragma unroll
        for (int g = 0; g < 8; ++g) {
            #pragma unroll
            for (int hf = 0; hf < 2; ++hf) {
                const int nt = 2 * g + hf;
                float2 bv = *reinterpret_cast<const float2*>(
                    smem + A_SBIAS + st * 512 + (nt * 8 + (lane & 3) * 2) * 4);
                uint32_t a01 = packh(fmaf(w[nt][0], C1, bv.x),
                                     fmaf(w[nt][1], C1, bv.y));
                uint32_t a23 = packh(fmaf(w[nt][2], C1, bv.x),
                                     fmaf(w[nt][3], C1, bv.y));
                uint32_t h01 = mexp2h2(a01);
                uint32_t h23 = mexp2h2(a23);
                ph[g][2 * hf]     = h01;
                ph[g][2 * hf + 1] = h23;
                __half2 t01 = *reinterpret_cast<__half2*>(&h01);
                __half2 t23 = *reinterpret_cast<__half2*>(&h23);
                l0 += __low2float(t01) + __high2float(t01);
                l1 += __low2float(t23) + __high2float(t23);
            }
        }

        // O += P V
        #pragma unroll
        for (int g = 0; g < 8; ++g) {
            #pragma unroll
            for (int np = 0; np < 4; ++np) {
                uint32_t vb[4];
                uint32_t row = g * 16 + (lane & 15);
                uint32_t col = np * 16 + ((lane >> 4) << 3);
                ldsm_x4t(vb, sV + row * AP + col * 2);
                mma_f16(oacc[2 * np],     ph[g], vb[0], vb[1]);
                mma_f16(oacc[2 * np + 1], ph[g], vb[2], vb[3]);
            }
        }

        __syncthreads();
        if (it + 2 < 32) {
            attn_load_kv(sb, st, t, k16, v16, bias2, (size_t)(it + 2) * 128, hcol);
            CP_COMMIT();
        } else {
            CP_COMMIT();
        }
    }

    l0 += __shfl_xor_sync(0xffffffffu, l0, 1);
    l0 += __shfl_xor_sync(0xffffffffu, l0, 2);
    l1 += __shfl_xor_sync(0xffffffffu, l1, 1);
    l1 += __shfl_xor_sync(0xffffffffu, l1, 2);
    float inv0 = 1.0f / l0, inv1 = 1.0f / l1;

    size_t r0 = qrow0 + wid * 16 + (lane >> 2);
    size_t r1 = r0 + 8;
    #pragma unroll
    for (int nt = 0; nt < 8; ++nt) {
        int c = hcol + nt * 8 + (lane & 3) * 2;
        *reinterpret_cast<uint32_t*>(o16 + r0 * DD + c) =
            packh(oacc[nt][0] * inv0, oacc[nt][1] * inv0);
        *reinterpret_cast<uint32_t*>(o16 + r1 * DD + c) =
            packh(oacc[nt][2] * inv1, oacc[nt][3] * inv1);
    }
}

// ---------------- conversion kernels ----------------------------------------
__global__ void cvt16_kernel(const float4* __restrict__ x,
                             __half2* __restrict__ y, int n4)
{
    int i = blockIdx.x * blockDim.x + threadIdx.x;
    if (i >= n4) return;
    float4 v = x[i];
    y[2 * i]     = __floats2half2_rn(v.x, v.y);
    y[2 * i + 1] = __floats2half2_rn(v.z, v.w);
}

__global__ void bias_scale_kernel(const float* __restrict__ b,
                                  float* __restrict__ b2, int n)
{
    int i = blockIdx.x * blockDim.x + threadIdx.x;
    if (i < n) b2[i] = fmaf(b[i], 1.44269504f, -ARG_SHIFT);
}

// 4x W[1024,1024] fp32 row-major -> W^T fp16 [N,K], batched over z (hi only)
__global__ void transpose4(const float* __restrict__ W0,
                           const float* __restrict__ W1,
                           const float* __restrict__ W2,
                           const float* __restrict__ W3,
                           half_t* __restrict__ T)
{
    __shared__ float tl[32][33];
    const int tx = threadIdx.x, ty = threadIdx.y;
    const int n0 = blockIdx.x * 32, k0 = blockIdx.y * 32;
    const int z = blockIdx.z;
    const float* W = (z == 0) ? W0 : (z == 1) ? W1 : (z == 2) ? W2 : W3;
    half_t* th = T + (size_t)z * DD * DD;
    #pragma unroll
    for (int i = 0; i < 4; ++i)
        tl[ty + i * 8][tx] = W[(size_t)(k0 + ty + i * 8) * DD + n0 + tx];
    __syncthreads();
    #pragma unroll
    for (int i = 0; i < 4; ++i) {
        float v = tl[tx][ty + i * 8];
        th[(size_t)(n0 + ty + i * 8) * DD + k0 + tx] = __float2half_rn(v);
    }
}

// ---------------- host launch -------------------------------------------------
extern "C" void kernel_launch(void* const* d_in, const int* in_sizes, int n_in,
                              void* d_out, int out_size)
{
    const float* query  = (const float*)d_in[0];
    const float* memory = (const float*)d_in[1];
    const float* bias   = (const float*)d_in[2];
    const float* W0 = (const float*)d_in[3];
    const float* W1 = (const float*)d_in[4];
    const float* W2 = (const float*)d_in[5];
    const float* W3 = (const float*)d_in[6];
    float* out = (float*)d_out;

    half_t *iq16, *im16, *wt, *q16, *k16, *v16, *a16;
    float* bias2;
    cudaGetSymbolAddress((void**)&iq16, gi_q16);
    cudaGetSymbolAddress((void**)&im16, gi_m16);
    cudaGetSymbolAddress((void**)&wt, g_wt);
    cudaGetSymbolAddress((void**)&bias2, g_bias2);
    cudaGetSymbolAddress((void**)&q16, g_q16);
    cudaGetSymbolAddress((void**)&k16, g_k16);
    cudaGetSymbolAddress((void**)&v16, g_v16);
    cudaGetSymbolAddress((void**)&a16, g_a16);

    const int SM_S = gsmem_bytes(2);
    const int SM_L = gsmem_bytes(4);

    static cudaStream_t s1 = nullptr, s2 = nullptr, s3 = nullptr;
    static cudaEvent_t ev[10] = {};
    static int attr_set = 0;
    if (!attr_set) {
        cudaFuncSetAttribute((const void*)gemm_mma<1, 2>,
                             cudaFuncAttributeMaxDynamicSharedMemorySize, SM_S);
        cudaFuncSetAttribute((const void*)gemm_mma<0, 2>,
                             cudaFuncAttributeMaxDynamicSharedMemorySize, SM_S);
        cudaFuncSetAttribute((const void*)gemm_mma<1, 4>,
                             cudaFuncAttributeMaxDynamicSharedMemorySize, SM_L);
        cudaFuncSetAttribute((const void*)attn_mma,
                             cudaFuncAttributeMaxDynamicSharedMemorySize, ATT_SMEM);
        cudaStreamCreateWithFlags(&s1, cudaStreamNonBlocking);
        cudaStreamCreateWithFlags(&s2, cudaStreamNonBlocking);
        cudaStreamCreateWithFlags(&s3, cudaStreamNonBlocking);
        for (int i = 0; i < 10; ++i)
            cudaEventCreateWithFlags(&ev[i], cudaEventDisableTiming);
        attr_set = 1;
    }
    cudaStream_t sd = (cudaStream_t)0;
    cudaEvent_t eF = ev[0], eT = ev[1], eC1 = ev[2], eQ = ev[3];
    cudaEvent_t eKV1 = ev[4], eKV2 = ev[5];

    const size_t HALF_M = (size_t)(BB / 2) * KL;

    // ---- fork ----
    cudaEventRecord(eF, sd);
    cudaStreamWaitEvent(s1, eF, 0);
    cudaStreamWaitEvent(s2, eF, 0);
    cudaStreamWaitEvent(s3, eF, 0);

    // s2: weight transpose only (eT gates the GEMMs; bias moved off this path)
    {
        dim3 thr(32, 8), grid(DD / 32, DD / 32, 4);
        transpose4<<<grid, thr, 0, s2>>>(W0, W1, W2, W3, wt);
        cudaEventRecord(eT, s2);
    }
    // s1: bias prescale (needed only by attention) + query chain
    {
        bias_scale_kernel<<<(BB * KL) / 256, 256, 0, s1>>>(bias, bias2, BB * KL);
        int n4 = (BB * QL * DD) / 4;
        cvt16_kernel<<<n4 / 256, 256, 0, s1>>>((const float4*)query, (__half2*)iq16, n4);
        cudaStreamWaitEvent(s1, eT, 0);
        dim3 grid(DD / 128, (BB * QL) / 64);
        gemm_mma<1, 2><<<grid, 128, SM_S, s1>>>(iq16, wt, nullptr, q16);
        cudaEventRecord(eQ, s1);
    }
    // sd: memory half 1 -> fp16, then merged K1+V1 (grid.z = {K, V})
    {
        int n4h = (int)(HALF_M * DD / 4);
        cvt16_kernel<<<n4h / 256, 256, 0, sd>>>((const float4*)memory, (__half2*)im16, n4h);
        cudaEventRecord(eC1, sd);
        cudaStreamWaitEvent(sd, eT, 0);
        dim3 grid(DD / 128, (int)(HALF_M / 128), 2);
        gemm_mma<1, 4><<<grid, 128, SM_L, sd>>>(im16, wt + (size_t)DD * DD, nullptr, k16,
                                                wt + 2 * (size_t)DD * DD, v16);
        cudaEventRecord(eKV1, sd);
    }
    // s3: memory half 2 -> fp16, then merged K2+V2
    {
        cudaStreamWaitEvent(s3, eC1, 0);
        int n4h = (int)(HALF_M * DD / 4);
        cvt16_kernel<<<n4h / 256, 256, 0, s3>>>(
            (const float4*)(memory + HALF_M * DD), (__half2*)(im16 + HALF_M * DD), n4h);
        cudaStreamWaitEvent(s3, eT, 0);
        dim3 grid(DD / 128, (int)(HALF_M / 128), 2);
        gemm_mma<1, 4><<<grid, 128, SM_L, s3>>>(im16 + HALF_M * DD,
                                                wt + (size_t)DD * DD, nullptr,
                                                k16 + HALF_M * DD,
                                                wt + 2 * (size_t)DD * DD,
                                                v16 + HALF_M * DD);
        cudaEventRecord(eKV2, s3);
    }

    // ---- per-batch attention + O-projection on 4 streams ----
    cudaStream_t bst[BB] = {sd, s2, s3, s1};
    for (int b = 0; b < BB; ++b) {
        cudaStream_t s = bst[b];
        if (b < 2) cudaStreamWaitEvent(s, eKV1, 0);
        else       cudaStreamWaitEvent(s, eKV2, 0);
        cudaStreamWaitEvent(s, eQ, 0);

        size_t qo = (size_t)b * QL * DD;
        size_t ko = (size_t)b * KL * DD;
        {
            dim3 grid(QL / 128, NH, 1);
            attn_mma<<<grid, 256, ATT_SMEM, s>>>(q16 + qo, k16 + ko, v16 + ko,
                                                 bias2 + (size_t)b * KL, a16 + qo);
        }
        {
            dim3 grid(DD / 128, QL / 64);
            gemm_mma<0, 2><<<grid, 128, SM_S, s>>>(a16 + qo, wt + 3 * (size_t)DD * DD,
                                                   out + qo, nullptr);
        }
        if (s != sd) {
            cudaEventRecord(ev[6 + b], s);
            cudaStreamWaitEvent(sd, ev[6 + b], 0);
        }
    }
}